// round 14
// baseline (speedup 1.0000x reference)
#include <cuda_runtime.h>
#include <cuda_fp16.h>
#include <cstdint>
#include <cstddef>

// ============================================================================
// out = softmax(Q K^T / sqrt(D), axis=k) @ V,  S=8192, D=1024, fp32 in/out.
// mma.sync m16n8k16 fp16->fp32, warp tile 64x64, BK=64, SW128 swizzle,
// 3-stage cp.async, single mid-chunk barrier, fused softmax epilogues,
// chunk-phase desync. NEW: wave-1 twin stagger sized to HALF the CTA
// lifetime (10240 cyc for GEMM1) so the twin's ~2048-cycle MUFU epilogue
// burst + prologue land mid-mainloop of the partner CTA on every wave.
// ============================================================================

#define SQ 8192
#define DM 1024

// ---------------- scratch ---------------------------------------------------
__device__ __half g_qh[(size_t)SQ * DM];            // Q * log2e/32, fp16
__device__ __half g_kh[(size_t)SQ * DM];            // K, fp16
__device__ __half g_vt[(size_t)DM * SQ];            // V^T, fp16 [d][s]
__device__ __half g_p [(size_t)SQ * SQ];            // exp(scores), fp16
__device__ float  g_l [SQ];                         // row sums of exp

// ---------------- helpers ---------------------------------------------------
__device__ __forceinline__ uint32_t smem_u32(const void* p) {
    uint32_t a;
    asm("{ .reg .u64 t; cvta.to.shared.u64 t, %1; cvt.u32.u64 %0, t; }"
        : "=r"(a) : "l"(p));
    return a;
}

__device__ __forceinline__ float ex2(float x) {
    float y;
    asm("ex2.approx.f32 %0, %1;" : "=f"(y) : "f"(x));
    return y;
}

__device__ __forceinline__ void cp16(uint32_t d, const void* s) {
    asm volatile("cp.async.cg.shared.global [%0], [%1], 16;" :: "r"(d), "l"(s));
}
__device__ __forceinline__ void cp_commit() { asm volatile("cp.async.commit_group;"); }
template <int N> __device__ __forceinline__ void cp_wait() {
    asm volatile("cp.async.wait_group %0;" :: "n"(N));
}

__device__ __forceinline__ void ldsm4(uint32_t* r, uint32_t a) {
    asm volatile("ldmatrix.sync.aligned.m8n8.x4.shared.b16 {%0,%1,%2,%3}, [%4];"
                 : "=r"(r[0]), "=r"(r[1]), "=r"(r[2]), "=r"(r[3]) : "r"(a));
}

__device__ __forceinline__ void mma16816(float* c, const uint32_t* a,
                                         uint32_t b0, uint32_t b1) {
    asm volatile(
        "mma.sync.aligned.m16n8k16.row.col.f32.f16.f16.f32 "
        "{%0,%1,%2,%3}, {%4,%5,%6,%7}, {%8,%9}, {%0,%1,%2,%3};"
        : "+f"(c[0]), "+f"(c[1]), "+f"(c[2]), "+f"(c[3])
        : "r"(a[0]), "r"(a[1]), "r"(a[2]), "r"(a[3]), "r"(b0), "r"(b1));
}

// ---------------- GEMM: C[M,N] = A[M,K] * B[N,K]^T ---------------------------
#define BN 128
#define BK 64
#define NST 3

template <int MT, typename T, bool EXPE, bool NORM, bool SWAPXY, int STAG>
__global__ void __launch_bounds__(128, 2)
k_gemm(const __half* __restrict__ A, const __half* __restrict__ B,
       T* __restrict__ C, float* __restrict__ l,
       int lda, int ldb, int ldc, int nch) {
    constexpr int BM = 32 * MT;
    constexpr int A_SM = BM * 128;
    constexpr int STG = A_SM + 128 * 128;

    extern __shared__ __align__(1024) char smem[];
    const uint32_t sb = smem_u32(smem);
    const int tid = threadIdx.x, lane = tid & 31, wid = tid >> 5;
    const int m0 = (SWAPXY ? blockIdx.y : blockIdx.x) * BM;
    const int n0 = (SWAPXY ? blockIdx.x : blockIdx.y) * BN;

    // chunk-phase desync: co-resident CTAs visit chunks half a sequence apart
    const int bidlin = blockIdx.y * gridDim.x + blockIdx.x;
    const int phase = ((bidlin / 148) & 1) ? (nch >> 1) : 0;

    // wave-1 twin stagger sized to ~half a CTA lifetime: the twin's epilogue
    // MUFU burst and prologue fill land mid-mainloop of the partner on every
    // subsequent wave (completion-driven starts propagate the offset).
    if (bidlin >= 148 && bidlin < 296) {
        const long long t0 = clock64();
        while (clock64() - t0 < STAG) { }
    }

    const __half* arow = A + (size_t)m0 * lda;
    const __half* brow = B + (size_t)n0 * ldb;

    const int c_r0 = tid >> 3;                 // cp.async row base
    const int c_ch = tid & 7;                  // 16B chunk

    const int g = lane >> 3, lr = lane & 7;
    const int wm0 = (wid >> 1) * (16 * MT);
    const int wn0 = (wid & 1) * 64;
    const uint32_t alm = (uint32_t)(lr << 4);
    const uint32_t ar0 = (uint32_t)((wm0 + lr + (g & 1) * 8) * 128);
    const uint32_t axm = (uint32_t)((g >> 1) << 4) ^ alm;
    const uint32_t br0 = (uint32_t)(A_SM + (wn0 + lr + (g >> 1) * 8) * 128);
    const uint32_t bxm = (uint32_t)((g & 1) << 4) ^ alm;

    float acc[MT][8][4];
#pragma unroll
    for (int i = 0; i < MT; i++)
#pragma unroll
        for (int j = 0; j < 8; j++)
#pragma unroll
            for (int c = 0; c < 4; c++) acc[i][j][c] = 0.f;

    // ---- prologue: pipeline positions 0..NST-2 ----
#pragma unroll
    for (int j = 0; j < NST - 1; j++) {
        const uint32_t s = sb + j * STG;
        const int kc = ((j + phase) & (nch - 1)) * BK;     // nch is pow2
#pragma unroll
        for (int it = 0; it < BM / 16; it++) {
            const int r = c_r0 + it * 16;
            cp16(s + r * 128 + ((c_ch ^ (r & 7)) << 4),
                 arow + (size_t)r * lda + kc + c_ch * 8);
        }
#pragma unroll
        for (int it = 0; it < 8; it++) {
            const int r = c_r0 + it * 16;
            cp16(s + A_SM + r * 128 + ((c_ch ^ (r & 7)) << 4),
                 brow + (size_t)r * ldb + kc + c_ch * 8);
        }
        cp_commit();
    }

    uint32_t afr[2][MT][4], bfr[2][4][4];

    // position 0 ready + visible, preload its kk0 fragments
    cp_wait<NST - 2>();
    __syncthreads();
#pragma unroll
    for (int mt = 0; mt < MT; mt++)
        ldsm4(afr[0][mt], sb + ar0 + mt * 2048 + (0u ^ axm));
#pragma unroll
    for (int nb = 0; nb < 4; nb++)
        ldsm4(bfr[0][nb], sb + br0 + nb * 2048 + (0u ^ bxm));

    // ---- main loop over pipeline positions ----
    for (int i = 0; i < nch; i++) {
        const int jl = i + NST - 1;
        if (jl < nch) {
            const uint32_t s = sb + (jl % NST) * STG;
            const int kc = ((jl + phase) & (nch - 1)) * BK;
#pragma unroll
            for (int it = 0; it < BM / 16; it++) {
                const int r = c_r0 + it * 16;
                cp16(s + r * 128 + ((c_ch ^ (r & 7)) << 4),
                     arow + (size_t)r * lda + kc + c_ch * 8);
            }
#pragma unroll
            for (int it = 0; it < 8; it++) {
                const int r = c_r0 + it * 16;
                cp16(s + A_SM + r * 128 + ((c_ch ^ (r & 7)) << 4),
                     brow + (size_t)r * ldb + kc + c_ch * 8);
            }
        }
        cp_commit();

        const uint32_t s = sb + (i % NST) * STG;

#pragma unroll
        for (int kk = 0; kk < 4; kk++) {
            if (kk < 3) {
                const uint32_t ko = (uint32_t)((kk + 1) << 5);
                const int nb_ = (kk + 1) & 1;
#pragma unroll
                for (int mt = 0; mt < MT; mt++)
                    ldsm4(afr[nb_][mt], s + ar0 + mt * 2048 + (ko ^ axm));
#pragma unroll
                for (int nb = 0; nb < 4; nb++)
                    ldsm4(bfr[nb_][nb], s + br0 + nb * 2048 + (ko ^ bxm));
            }
            if (kk == 2) {
                cp_wait<1>();        // this thread's groups <= i+1 drained
                __syncthreads();     // position i+1 globally visible; orders
                                     // position i-1 reads before slot reuse
            }
            const int cb = kk & 1;
#pragma unroll
            for (int mt = 0; mt < MT; mt++)
#pragma unroll
                for (int nt = 0; nt < 8; nt++)
                    mma16816(acc[mt][nt], afr[cb][mt],
                             bfr[cb][nt >> 1][(nt & 1) * 2],
                             bfr[cb][nt >> 1][(nt & 1) * 2 + 1]);
        }

        if (i + 1 < nch) {
            const uint32_t sn = sb + ((i + 1) % NST) * STG;
#pragma unroll
            for (int mt = 0; mt < MT; mt++)
                ldsm4(afr[0][mt], sn + ar0 + mt * 2048 + (0u ^ axm));
#pragma unroll
            for (int nb = 0; nb < 4; nb++)
                ldsm4(bfr[0][nb], sn + br0 + nb * 2048 + (0u ^ bxm));
        }
    }

    // ---- epilogue ----
    const int rr = lane >> 2, cc = 2 * (lane & 3);
    T* cw = C + (size_t)(m0 + wm0) * ldc + (n0 + wn0);

    float linv[MT][2];
    if constexpr (NORM) {
        float* ls = reinterpret_cast<float*>(smem);
        __syncthreads();
        if (tid < BM) ls[tid] = 1.f / l[m0 + tid];
        __syncthreads();
#pragma unroll
        for (int mt = 0; mt < MT; mt++) {
            linv[mt][0] = ls[wm0 + mt * 16 + rr];
            linv[mt][1] = ls[wm0 + mt * 16 + rr + 8];
        }
    }

#pragma unroll
    for (int mt = 0; mt < MT; mt++) {
        if constexpr (EXPE) {
            float sA = 0.f, sB = 0.f;
#pragma unroll
            for (int nt = 0; nt < 8; nt++) {
                float e0 = ex2(acc[mt][nt][0]);
                float e1 = ex2(acc[mt][nt][1]);
                float e2 = ex2(acc[mt][nt][2]);
                float e3 = ex2(acc[mt][nt][3]);
                sA += e0 + e1;
                sB += e2 + e3;
                __half2 v0 = __floats2half2_rn(e0, e1);
                __half2 v1 = __floats2half2_rn(e2, e3);
                *reinterpret_cast<__half2*>(cw + (size_t)(mt * 16 + rr) * ldc + nt * 8 + cc) = v0;
                *reinterpret_cast<__half2*>(cw + (size_t)(mt * 16 + rr + 8) * ldc + nt * 8 + cc) = v1;
            }
            sA += __shfl_xor_sync(0xFFFFFFFFu, sA, 1);
            sA += __shfl_xor_sync(0xFFFFFFFFu, sA, 2);
            sB += __shfl_xor_sync(0xFFFFFFFFu, sB, 1);
            sB += __shfl_xor_sync(0xFFFFFFFFu, sB, 2);
            if ((lane & 3) == 0) {
                atomicAdd(&l[m0 + wm0 + mt * 16 + rr], sA);
                atomicAdd(&l[m0 + wm0 + mt * 16 + rr + 8], sB);
            }
        } else if constexpr (NORM) {
#pragma unroll
            for (int nt = 0; nt < 8; nt++) {
                float2 v0 = make_float2(acc[mt][nt][0] * linv[mt][0],
                                        acc[mt][nt][1] * linv[mt][0]);
                float2 v1 = make_float2(acc[mt][nt][2] * linv[mt][1],
                                        acc[mt][nt][3] * linv[mt][1]);
                *reinterpret_cast<float2*>(cw + (size_t)(mt * 16 + rr) * ldc + nt * 8 + cc) = v0;
                *reinterpret_cast<float2*>(cw + (size_t)(mt * 16 + rr + 8) * ldc + nt * 8 + cc) = v1;
            }
        } else {
#pragma unroll
            for (int nt = 0; nt < 8; nt++) {
                float2 v0 = make_float2(acc[mt][nt][0], acc[mt][nt][1]);
                float2 v1 = make_float2(acc[mt][nt][2], acc[mt][nt][3]);
                *reinterpret_cast<float2*>(cw + (size_t)(mt * 16 + rr) * ldc + nt * 8 + cc) = v0;
                *reinterpret_cast<float2*>(cw + (size_t)(mt * 16 + rr + 8) * ldc + nt * 8 + cc) = v1;
            }
        }
    }
}

// ---------------- fused prep: zero l, cvt Q, cvt K, transpose V --------------
#define QK_BLKS (SQ * DM / 4 / 256)          // 8192
#define TR_BLKS ((DM / 32) * (SQ / 64))      // 4096

__global__ void __launch_bounds__(256)
k_prep(const float* __restrict__ q, const float* __restrict__ k,
       const float* __restrict__ v, __half* __restrict__ qh,
       __half* __restrict__ kh, __half* __restrict__ vt,
       float* __restrict__ l) {
    const int bx = blockIdx.x;
    if (bx < 2 * QK_BLKS) {
        const bool isq = bx < QK_BLKS;
        const int i = (isq ? bx : bx - QK_BLKS) * 256 + threadIdx.x;
        const float sc = isq ? 0.045084937554f : 1.0f;   // log2e/32
        float4 x = reinterpret_cast<const float4*>(isq ? q : k)[i];
        __half2* o = reinterpret_cast<__half2*>(isq ? qh : kh);
        o[2 * i]     = __floats2half2_rn(x.x * sc, x.y * sc);
        o[2 * i + 1] = __floats2half2_rn(x.z * sc, x.w * sc);
    } else if (bx < 2 * QK_BLKS + TR_BLKS) {
        __shared__ float tile[64][33];                   // [s_local][d_local]
        const int b = bx - 2 * QK_BLKS;
        const int d0 = (b % (DM / 32)) * 32, s0 = (b / (DM / 32)) * 64;
        const int tx = threadIdx.x & 31, ty = threadIdx.x >> 5;
#pragma unroll
        for (int i = 0; i < 8; i++)
            tile[ty + i * 8][tx] = v[(size_t)(s0 + ty + i * 8) * DM + d0 + tx];
        __syncthreads();
        __half2* vt2 = reinterpret_cast<__half2*>(vt);
#pragma unroll
        for (int j = 0; j < 4; j++) {
            const int dl = ty + j * 8;
            vt2[(size_t)(d0 + dl) * (SQ / 2) + s0 / 2 + tx] =
                __floats2half2_rn(tile[2 * tx][dl], tile[2 * tx + 1][dl]);
        }
    } else {
        const int i = (bx - 2 * QK_BLKS - TR_BLKS) * 256 + threadIdx.x;
        l[i] = 0.f;
    }
}

// ---------------- launcher ---------------------------------------------------
extern "C" void kernel_launch(void* const* d_in, const int* in_sizes, int n_in,
                              void* d_out, int out_size) {
    const float* q = (const float*)d_in[0];
    const float* k = (const float*)d_in[1];
    const float* v = (const float*)d_in[2];
    float* out = (float*)d_out;

    __half *qh, *kh, *vt, *p;
    float* l;
    cudaGetSymbolAddress((void**)&qh, g_qh);
    cudaGetSymbolAddress((void**)&kh, g_kh);
    cudaGetSymbolAddress((void**)&vt, g_vt);
    cudaGetSymbolAddress((void**)&p,  g_p);
    cudaGetSymbolAddress((void**)&l,  g_l);

    constexpr int SMEM1 = NST * (128 * 128 + 128 * 128);   // 98304 B

    cudaFuncSetAttribute((void*)k_gemm<4, __half, true, false, false, 10240>,
                         cudaFuncAttributeMaxDynamicSharedMemorySize, SMEM1);
    cudaFuncSetAttribute((void*)k_gemm<4, float, false, true, true, 4096>,
                         cudaFuncAttributeMaxDynamicSharedMemorySize, SMEM1);

    // fused prep: cvt Q (scaled), cvt K, transpose V, zero l
    k_prep<<<2 * QK_BLKS + TR_BLKS + SQ / 256, 256>>>(q, k, v, qh, kh, vt, l);

    // P' = exp2(Qs K^T) = exp(Q K^T / 32) : M=N=8192, K=1024 -> fp16, sums -> l
    // stagger = 10240 cyc ~ half CTA lifetime (hides the MUFU epilogue burst)
    k_gemm<4, __half, true, false, false, 10240>
        <<<dim3(SQ / 128, SQ / 128), 128, SMEM1>>>(
        qh, kh, p, l, DM, DM, SQ, DM / BK);

    // out = (P' V) / l : M=8192, N=1024, K=8192 -> fp32
    k_gemm<4, float, false, true, true, 4096>
        <<<dim3(DM / 128, SQ / 128), 128, SMEM1>>>(
        p, vt, out, l, SQ, SQ, DM, SQ / BK);
}

// round 15
// speedup vs baseline: 1.0133x; 1.0133x over previous
#include <cuda_runtime.h>
#include <cuda_fp16.h>
#include <cstdint>
#include <cstddef>

// ============================================================================
// out = softmax(Q K^T / sqrt(D), axis=k) @ V,  S=8192, D=1024, fp32 in/out.
// mma.sync m16n8k16 fp16->fp32, warp tile 64x64, BK=64, SW128 swizzle,
// 3-stage cp.async, single mid-chunk barrier, fused softmax epilogues,
// chunk-phase desync + small wave-1 stagger. NEW: GEMM1 epilogue uses
// ex2.approx.f16x2 (one MUFU per value-pair, result is the stored half2),
// halving the 2048-cycle/SMSP MUFU burst; prep convert does 2 float4/thread.
// ============================================================================

#define SQ 8192
#define DM 1024

// ---------------- scratch ---------------------------------------------------
__device__ __half g_qh[(size_t)SQ * DM];            // Q * log2e/32, fp16
__device__ __half g_kh[(size_t)SQ * DM];            // K, fp16
__device__ __half g_vt[(size_t)DM * SQ];            // V^T, fp16 [d][s]
__device__ __half g_p [(size_t)SQ * SQ];            // exp(scores), fp16
__device__ float  g_l [SQ];                         // row sums of exp

// ---------------- helpers ---------------------------------------------------
__device__ __forceinline__ uint32_t smem_u32(const void* p) {
    uint32_t a;
    asm("{ .reg .u64 t; cvta.to.shared.u64 t, %1; cvt.u32.u64 %0, t; }"
        : "=r"(a) : "l"(p));
    return a;
}

// pack two fp32 (already in log2 domain) to f16x2 and exponentiate in one MUFU
__device__ __forceinline__ uint32_t ex2_f16x2(float lo, float hi) {
    uint32_t h, e;
    asm("cvt.rn.f16x2.f32 %0, %1, %2;" : "=r"(h) : "f"(hi), "f"(lo));
    asm("ex2.approx.f16x2 %0, %1;" : "=r"(e) : "r"(h));
    return e;
}

__device__ __forceinline__ void cp16(uint32_t d, const void* s) {
    asm volatile("cp.async.cg.shared.global [%0], [%1], 16;" :: "r"(d), "l"(s));
}
__device__ __forceinline__ void cp_commit() { asm volatile("cp.async.commit_group;"); }
template <int N> __device__ __forceinline__ void cp_wait() {
    asm volatile("cp.async.wait_group %0;" :: "n"(N));
}

__device__ __forceinline__ void ldsm4(uint32_t* r, uint32_t a) {
    asm volatile("ldmatrix.sync.aligned.m8n8.x4.shared.b16 {%0,%1,%2,%3}, [%4];"
                 : "=r"(r[0]), "=r"(r[1]), "=r"(r[2]), "=r"(r[3]) : "r"(a));
}

__device__ __forceinline__ void mma16816(float* c, const uint32_t* a,
                                         uint32_t b0, uint32_t b1) {
    asm volatile(
        "mma.sync.aligned.m16n8k16.row.col.f32.f16.f16.f32 "
        "{%0,%1,%2,%3}, {%4,%5,%6,%7}, {%8,%9}, {%0,%1,%2,%3};"
        : "+f"(c[0]), "+f"(c[1]), "+f"(c[2]), "+f"(c[3])
        : "r"(a[0]), "r"(a[1]), "r"(a[2]), "r"(a[3]), "r"(b0), "r"(b1));
}

// ---------------- GEMM: C[M,N] = A[M,K] * B[N,K]^T ---------------------------
#define BN 128
#define BK 64
#define NST 3

template <int MT, typename T, bool EXPE, bool NORM, bool SWAPXY>
__global__ void __launch_bounds__(128, 2)
k_gemm(const __half* __restrict__ A, const __half* __restrict__ B,
       T* __restrict__ C, float* __restrict__ l,
       int lda, int ldb, int ldc, int nch) {
    constexpr int BM = 32 * MT;
    constexpr int A_SM = BM * 128;
    constexpr int STG = A_SM + 128 * 128;

    extern __shared__ __align__(1024) char smem[];
    const uint32_t sb = smem_u32(smem);
    const int tid = threadIdx.x, lane = tid & 31, wid = tid >> 5;
    const int m0 = (SWAPXY ? blockIdx.y : blockIdx.x) * BM;
    const int n0 = (SWAPXY ? blockIdx.x : blockIdx.y) * BN;

    // chunk-phase desync: co-resident CTAs visit chunks half a sequence apart
    const int bidlin = blockIdx.y * gridDim.x + blockIdx.x;
    const int phase = ((bidlin / 148) & 1) ? (nch >> 1) : 0;

    // small wave-1 twin stagger (r12 value; larger was neutral)
    if (bidlin >= 148 && bidlin < 296) {
        const long long t0 = clock64();
        while (clock64() - t0 < 4096) { }
    }

    const __half* arow = A + (size_t)m0 * lda;
    const __half* brow = B + (size_t)n0 * ldb;

    const int c_r0 = tid >> 3;                 // cp.async row base
    const int c_ch = tid & 7;                  // 16B chunk

    const int g = lane >> 3, lr = lane & 7;
    const int wm0 = (wid >> 1) * (16 * MT);
    const int wn0 = (wid & 1) * 64;
    const uint32_t alm = (uint32_t)(lr << 4);
    const uint32_t ar0 = (uint32_t)((wm0 + lr + (g & 1) * 8) * 128);
    const uint32_t axm = (uint32_t)((g >> 1) << 4) ^ alm;
    const uint32_t br0 = (uint32_t)(A_SM + (wn0 + lr + (g >> 1) * 8) * 128);
    const uint32_t bxm = (uint32_t)((g & 1) << 4) ^ alm;

    float acc[MT][8][4];
#pragma unroll
    for (int i = 0; i < MT; i++)
#pragma unroll
        for (int j = 0; j < 8; j++)
#pragma unroll
            for (int c = 0; c < 4; c++) acc[i][j][c] = 0.f;

    // ---- prologue: pipeline positions 0..NST-2 ----
#pragma unroll
    for (int j = 0; j < NST - 1; j++) {
        const uint32_t s = sb + j * STG;
        const int kc = ((j + phase) & (nch - 1)) * BK;     // nch is pow2
#pragma unroll
        for (int it = 0; it < BM / 16; it++) {
            const int r = c_r0 + it * 16;
            cp16(s + r * 128 + ((c_ch ^ (r & 7)) << 4),
                 arow + (size_t)r * lda + kc + c_ch * 8);
        }
#pragma unroll
        for (int it = 0; it < 8; it++) {
            const int r = c_r0 + it * 16;
            cp16(s + A_SM + r * 128 + ((c_ch ^ (r & 7)) << 4),
                 brow + (size_t)r * ldb + kc + c_ch * 8);
        }
        cp_commit();
    }

    uint32_t afr[2][MT][4], bfr[2][4][4];

    // position 0 ready + visible, preload its kk0 fragments
    cp_wait<NST - 2>();
    __syncthreads();
#pragma unroll
    for (int mt = 0; mt < MT; mt++)
        ldsm4(afr[0][mt], sb + ar0 + mt * 2048 + (0u ^ axm));
#pragma unroll
    for (int nb = 0; nb < 4; nb++)
        ldsm4(bfr[0][nb], sb + br0 + nb * 2048 + (0u ^ bxm));

    // ---- main loop over pipeline positions ----
    for (int i = 0; i < nch; i++) {
        const int jl = i + NST - 1;
        if (jl < nch) {
            const uint32_t s = sb + (jl % NST) * STG;
            const int kc = ((jl + phase) & (nch - 1)) * BK;
#pragma unroll
            for (int it = 0; it < BM / 16; it++) {
                const int r = c_r0 + it * 16;
                cp16(s + r * 128 + ((c_ch ^ (r & 7)) << 4),
                     arow + (size_t)r * lda + kc + c_ch * 8);
            }
#pragma unroll
            for (int it = 0; it < 8; it++) {
                const int r = c_r0 + it * 16;
                cp16(s + A_SM + r * 128 + ((c_ch ^ (r & 7)) << 4),
                     brow + (size_t)r * ldb + kc + c_ch * 8);
            }
        }
        cp_commit();

        const uint32_t s = sb + (i % NST) * STG;

#pragma unroll
        for (int kk = 0; kk < 4; kk++) {
            if (kk < 3) {
                const uint32_t ko = (uint32_t)((kk + 1) << 5);
                const int nb_ = (kk + 1) & 1;
#pragma unroll
                for (int mt = 0; mt < MT; mt++)
                    ldsm4(afr[nb_][mt], s + ar0 + mt * 2048 + (ko ^ axm));
#pragma unroll
                for (int nb = 0; nb < 4; nb++)
                    ldsm4(bfr[nb_][nb], s + br0 + nb * 2048 + (ko ^ bxm));
            }
            if (kk == 2) {
                cp_wait<1>();        // this thread's groups <= i+1 drained
                __syncthreads();     // position i+1 globally visible; orders
                                     // position i-1 reads before slot reuse
            }
            const int cb = kk & 1;
#pragma unroll
            for (int mt = 0; mt < MT; mt++)
#pragma unroll
                for (int nt = 0; nt < 8; nt++)
                    mma16816(acc[mt][nt], afr[cb][mt],
                             bfr[cb][nt >> 1][(nt & 1) * 2],
                             bfr[cb][nt >> 1][(nt & 1) * 2 + 1]);
        }

        if (i + 1 < nch) {
            const uint32_t sn = sb + ((i + 1) % NST) * STG;
#pragma unroll
            for (int mt = 0; mt < MT; mt++)
                ldsm4(afr[0][mt], sn + ar0 + mt * 2048 + (0u ^ axm));
#pragma unroll
            for (int nb = 0; nb < 4; nb++)
                ldsm4(bfr[0][nb], sn + br0 + nb * 2048 + (0u ^ bxm));
        }
    }

    // ---- epilogue ----
    const int rr = lane >> 2, cc = 2 * (lane & 3);
    T* cw = C + (size_t)(m0 + wm0) * ldc + (n0 + wn0);

    float linv[MT][2];
    if constexpr (NORM) {
        float* ls = reinterpret_cast<float*>(smem);
        __syncthreads();
        if (tid < BM) ls[tid] = 1.f / l[m0 + tid];
        __syncthreads();
#pragma unroll
        for (int mt = 0; mt < MT; mt++) {
            linv[mt][0] = ls[wm0 + mt * 16 + rr];
            linv[mt][1] = ls[wm0 + mt * 16 + rr + 8];
        }
    }

#pragma unroll
    for (int mt = 0; mt < MT; mt++) {
        if constexpr (EXPE) {
            // acc in log2 domain; one f16x2 MUFU per pair, result = stored half2
            float sA = 0.f, sB = 0.f;
#pragma unroll
            for (int nt = 0; nt < 8; nt++) {
                const uint32_t e0 = ex2_f16x2(acc[mt][nt][0], acc[mt][nt][1]);
                const uint32_t e1 = ex2_f16x2(acc[mt][nt][2], acc[mt][nt][3]);
                *reinterpret_cast<uint32_t*>(cw + (size_t)(mt * 16 + rr) * ldc + nt * 8 + cc) = e0;
                *reinterpret_cast<uint32_t*>(cw + (size_t)(mt * 16 + rr + 8) * ldc + nt * 8 + cc) = e1;
                const float2 f0 = __half22float2(*reinterpret_cast<const __half2*>(&e0));
                const float2 f1 = __half22float2(*reinterpret_cast<const __half2*>(&e1));
                sA += f0.x + f0.y;
                sB += f1.x + f1.y;
            }
            sA += __shfl_xor_sync(0xFFFFFFFFu, sA, 1);
            sA += __shfl_xor_sync(0xFFFFFFFFu, sA, 2);
            sB += __shfl_xor_sync(0xFFFFFFFFu, sB, 1);
            sB += __shfl_xor_sync(0xFFFFFFFFu, sB, 2);
            if ((lane & 3) == 0) {
                atomicAdd(&l[m0 + wm0 + mt * 16 + rr], sA);
                atomicAdd(&l[m0 + wm0 + mt * 16 + rr + 8], sB);
            }
        } else if constexpr (NORM) {
#pragma unroll
            for (int nt = 0; nt < 8; nt++) {
                float2 v0 = make_float2(acc[mt][nt][0] * linv[mt][0],
                                        acc[mt][nt][1] * linv[mt][0]);
                float2 v1 = make_float2(acc[mt][nt][2] * linv[mt][1],
                                        acc[mt][nt][3] * linv[mt][1]);
                *reinterpret_cast<float2*>(cw + (size_t)(mt * 16 + rr) * ldc + nt * 8 + cc) = v0;
                *reinterpret_cast<float2*>(cw + (size_t)(mt * 16 + rr + 8) * ldc + nt * 8 + cc) = v1;
            }
        } else {
#pragma unroll
            for (int nt = 0; nt < 8; nt++) {
                float2 v0 = make_float2(acc[mt][nt][0], acc[mt][nt][1]);
                float2 v1 = make_float2(acc[mt][nt][2], acc[mt][nt][3]);
                *reinterpret_cast<float2*>(cw + (size_t)(mt * 16 + rr) * ldc + nt * 8 + cc) = v0;
                *reinterpret_cast<float2*>(cw + (size_t)(mt * 16 + rr + 8) * ldc + nt * 8 + cc) = v1;
            }
        }
    }
}

// ---------------- fused prep: zero l, cvt Q, cvt K, transpose V --------------
// Q/K convert: 2 float4 per thread (more MLP -> higher DRAM utilization).
#define QK_BLKS (SQ * DM / 8 / 256)          // 4096
#define TR_BLKS ((DM / 32) * (SQ / 64))      // 4096

__global__ void __launch_bounds__(256)
k_prep(const float* __restrict__ q, const float* __restrict__ k,
       const float* __restrict__ v, __half* __restrict__ qh,
       __half* __restrict__ kh, __half* __restrict__ vt,
       float* __restrict__ l) {
    const int bx = blockIdx.x;
    if (bx < 2 * QK_BLKS) {
        const bool isq = bx < QK_BLKS;
        const int base = ((isq ? bx : bx - QK_BLKS) * 256 + threadIdx.x) * 2;
        const float sc = isq ? 0.045084937554f : 1.0f;   // log2e/32
        const float4* in = reinterpret_cast<const float4*>(isq ? q : k);
        __half2* o = reinterpret_cast<__half2*>(isq ? qh : kh);
#pragma unroll
        for (int u = 0; u < 2; u++) {
            float4 x = in[base + u];
            o[2 * (base + u)]     = __floats2half2_rn(x.x * sc, x.y * sc);
            o[2 * (base + u) + 1] = __floats2half2_rn(x.z * sc, x.w * sc);
        }
    } else if (bx < 2 * QK_BLKS + TR_BLKS) {
        __shared__ float tile[64][33];                   // [s_local][d_local]
        const int b = bx - 2 * QK_BLKS;
        const int d0 = (b % (DM / 32)) * 32, s0 = (b / (DM / 32)) * 64;
        const int tx = threadIdx.x & 31, ty = threadIdx.x >> 5;
#pragma unroll
        for (int i = 0; i < 8; i++)
            tile[ty + i * 8][tx] = v[(size_t)(s0 + ty + i * 8) * DM + d0 + tx];
        __syncthreads();
        __half2* vt2 = reinterpret_cast<__half2*>(vt);
#pragma unroll
        for (int j = 0; j < 4; j++) {
            const int dl = ty + j * 8;
            vt2[(size_t)(d0 + dl) * (SQ / 2) + s0 / 2 + tx] =
                __floats2half2_rn(tile[2 * tx][dl], tile[2 * tx + 1][dl]);
        }
    } else {
        const int i = (bx - 2 * QK_BLKS - TR_BLKS) * 256 + threadIdx.x;
        l[i] = 0.f;
    }
}

// ---------------- launcher ---------------------------------------------------
extern "C" void kernel_launch(void* const* d_in, const int* in_sizes, int n_in,
                              void* d_out, int out_size) {
    const float* q = (const float*)d_in[0];
    const float* k = (const float*)d_in[1];
    const float* v = (const float*)d_in[2];
    float* out = (float*)d_out;

    __half *qh, *kh, *vt, *p;
    float* l;
    cudaGetSymbolAddress((void**)&qh, g_qh);
    cudaGetSymbolAddress((void**)&kh, g_kh);
    cudaGetSymbolAddress((void**)&vt, g_vt);
    cudaGetSymbolAddress((void**)&p,  g_p);
    cudaGetSymbolAddress((void**)&l,  g_l);

    constexpr int SMEM1 = NST * (128 * 128 + 128 * 128);   // 98304 B

    cudaFuncSetAttribute((void*)k_gemm<4, __half, true, false, false>,
                         cudaFuncAttributeMaxDynamicSharedMemorySize, SMEM1);
    cudaFuncSetAttribute((void*)k_gemm<4, float, false, true, true>,
                         cudaFuncAttributeMaxDynamicSharedMemorySize, SMEM1);

    // fused prep: cvt Q (scaled), cvt K, transpose V, zero l
    k_prep<<<2 * QK_BLKS + TR_BLKS + SQ / 256, 256>>>(q, k, v, qh, kh, vt, l);

    // P' = exp2(Qs K^T) = exp(Q K^T / 32) : M=N=8192, K=1024 -> fp16, sums -> l
    k_gemm<4, __half, true, false, false><<<dim3(SQ / 128, SQ / 128), 128, SMEM1>>>(
        qh, kh, p, l, DM, DM, SQ, DM / BK);

    // out = (P' V) / l : M=8192, N=1024, K=8192 -> fp32
    k_gemm<4, float, false, true, true><<<dim3(DM / 128, SQ / 128), 128, SMEM1>>>(
        p, vt, out, l, SQ, SQ, DM, SQ / BK);
}

// round 16
// speedup vs baseline: 1.0332x; 1.0196x over previous
#include <cuda_runtime.h>
#include <cuda_fp16.h>
#include <cstdint>
#include <cstddef>

// ============================================================================
// out = softmax(Q K^T / sqrt(D), axis=k) @ V,  S=8192, D=1024, fp32 in/out.
// GEMM1: 128x128 CTA, 2 CTA/SM (twin-hides the MUFU exp epilogue),
//        ex2.approx.f16x2 epilogue, row sums via atomics.
// GEMM2: 128x256 CTA, 256 thr, 1 CTA/SM (lower fragment-BW per MAC; prologue
//        amortized over nch=128), normalize epilogue.
// Both: mma.sync m16n8k16 fp16->fp32, warp tile 64x64, BK=64, SW128 swizzle,
// 3-stage cp.async, single mid-chunk barrier, chunk-phase desync.
// ============================================================================

#define SQ 8192
#define DM 1024

// ---------------- scratch ---------------------------------------------------
__device__ __half g_qh[(size_t)SQ * DM];            // Q * log2e/32, fp16
__device__ __half g_kh[(size_t)SQ * DM];            // K, fp16
__device__ __half g_vt[(size_t)DM * SQ];            // V^T, fp16 [d][s]
__device__ __half g_p [(size_t)SQ * SQ];            // exp(scores), fp16
__device__ float  g_l [SQ];                         // row sums of exp

// ---------------- helpers ---------------------------------------------------
__device__ __forceinline__ uint32_t smem_u32(const void* p) {
    uint32_t a;
    asm("{ .reg .u64 t; cvta.to.shared.u64 t, %1; cvt.u32.u64 %0, t; }"
        : "=r"(a) : "l"(p));
    return a;
}

// pack two fp32 (log2 domain) to f16x2 and exponentiate in one MUFU
__device__ __forceinline__ uint32_t ex2_f16x2(float lo, float hi) {
    uint32_t h, e;
    asm("cvt.rn.f16x2.f32 %0, %1, %2;" : "=r"(h) : "f"(hi), "f"(lo));
    asm("ex2.approx.f16x2 %0, %1;" : "=r"(e) : "r"(h));
    return e;
}

__device__ __forceinline__ void cp16(uint32_t d, const void* s) {
    asm volatile("cp.async.cg.shared.global [%0], [%1], 16;" :: "r"(d), "l"(s));
}
__device__ __forceinline__ void cp_commit() { asm volatile("cp.async.commit_group;"); }
template <int N> __device__ __forceinline__ void cp_wait() {
    asm volatile("cp.async.wait_group %0;" :: "n"(N));
}

__device__ __forceinline__ void ldsm4(uint32_t* r, uint32_t a) {
    asm volatile("ldmatrix.sync.aligned.m8n8.x4.shared.b16 {%0,%1,%2,%3}, [%4];"
                 : "=r"(r[0]), "=r"(r[1]), "=r"(r[2]), "=r"(r[3]) : "r"(a));
}

__device__ __forceinline__ void mma16816(float* c, const uint32_t* a,
                                         uint32_t b0, uint32_t b1) {
    asm volatile(
        "mma.sync.aligned.m16n8k16.row.col.f32.f16.f16.f32 "
        "{%0,%1,%2,%3}, {%4,%5,%6,%7}, {%8,%9}, {%0,%1,%2,%3};"
        : "+f"(c[0]), "+f"(c[1]), "+f"(c[2]), "+f"(c[3])
        : "r"(a[0]), "r"(a[1]), "r"(a[2]), "r"(a[3]), "r"(b0), "r"(b1));
}

#define BK 64
#define NST 3

// ================= GEMM1: 128x128, 128 thr, 2 CTA/SM, exp epilogue ==========
__global__ void __launch_bounds__(128, 2)
k_gemm1(const __half* __restrict__ A, const __half* __restrict__ B,
        __half* __restrict__ C, float* __restrict__ l,
        int lda, int ldb, int ldc, int nch) {
    constexpr int MT = 4;
    constexpr int BM = 128;
    constexpr int A_SM = BM * 128;
    constexpr int STG = A_SM + 128 * 128;

    extern __shared__ __align__(1024) char smem[];
    const uint32_t sb = smem_u32(smem);
    const int tid = threadIdx.x, lane = tid & 31, wid = tid >> 5;
    const int m0 = blockIdx.x * BM, n0 = blockIdx.y * 128;

    const int bidlin = blockIdx.y * gridDim.x + blockIdx.x;
    const int phase = ((bidlin / 148) & 1) ? (nch >> 1) : 0;
    if (bidlin >= 148 && bidlin < 296) {
        const long long t0 = clock64();
        while (clock64() - t0 < 4096) { }
    }

    const __half* arow = A + (size_t)m0 * lda;
    const __half* brow = B + (size_t)n0 * ldb;

    const int c_r0 = tid >> 3, c_ch = tid & 7;
    const int g = lane >> 3, lr = lane & 7;
    const int wm0 = (wid >> 1) * 64, wn0 = (wid & 1) * 64;
    const uint32_t alm = (uint32_t)(lr << 4);
    const uint32_t ar0 = (uint32_t)((wm0 + lr + (g & 1) * 8) * 128);
    const uint32_t axm = (uint32_t)((g >> 1) << 4) ^ alm;
    const uint32_t br0 = (uint32_t)(A_SM + (wn0 + lr + (g >> 1) * 8) * 128);
    const uint32_t bxm = (uint32_t)((g & 1) << 4) ^ alm;

    float acc[MT][8][4];
#pragma unroll
    for (int i = 0; i < MT; i++)
#pragma unroll
        for (int j = 0; j < 8; j++)
#pragma unroll
            for (int c = 0; c < 4; c++) acc[i][j][c] = 0.f;

#pragma unroll
    for (int j = 0; j < NST - 1; j++) {
        const uint32_t s = sb + j * STG;
        const int kc = ((j + phase) & (nch - 1)) * BK;
#pragma unroll
        for (int it = 0; it < 8; it++) {
            const int r = c_r0 + it * 16;
            cp16(s + r * 128 + ((c_ch ^ (r & 7)) << 4),
                 arow + (size_t)r * lda + kc + c_ch * 8);
        }
#pragma unroll
        for (int it = 0; it < 8; it++) {
            const int r = c_r0 + it * 16;
            cp16(s + A_SM + r * 128 + ((c_ch ^ (r & 7)) << 4),
                 brow + (size_t)r * ldb + kc + c_ch * 8);
        }
        cp_commit();
    }

    uint32_t afr[2][MT][4], bfr[2][4][4];
    cp_wait<NST - 2>();
    __syncthreads();
#pragma unroll
    for (int mt = 0; mt < MT; mt++)
        ldsm4(afr[0][mt], sb + ar0 + mt * 2048 + (0u ^ axm));
#pragma unroll
    for (int nb = 0; nb < 4; nb++)
        ldsm4(bfr[0][nb], sb + br0 + nb * 2048 + (0u ^ bxm));

    for (int i = 0; i < nch; i++) {
        const int jl = i + NST - 1;
        if (jl < nch) {
            const uint32_t s = sb + (jl % NST) * STG;
            const int kc = ((jl + phase) & (nch - 1)) * BK;
#pragma unroll
            for (int it = 0; it < 8; it++) {
                const int r = c_r0 + it * 16;
                cp16(s + r * 128 + ((c_ch ^ (r & 7)) << 4),
                     arow + (size_t)r * lda + kc + c_ch * 8);
            }
#pragma unroll
            for (int it = 0; it < 8; it++) {
                const int r = c_r0 + it * 16;
                cp16(s + A_SM + r * 128 + ((c_ch ^ (r & 7)) << 4),
                     brow + (size_t)r * ldb + kc + c_ch * 8);
            }
        }
        cp_commit();

        const uint32_t s = sb + (i % NST) * STG;
#pragma unroll
        for (int kk = 0; kk < 4; kk++) {
            if (kk < 3) {
                const uint32_t ko = (uint32_t)((kk + 1) << 5);
                const int nb_ = (kk + 1) & 1;
#pragma unroll
                for (int mt = 0; mt < MT; mt++)
                    ldsm4(afr[nb_][mt], s + ar0 + mt * 2048 + (ko ^ axm));
#pragma unroll
                for (int nb = 0; nb < 4; nb++)
                    ldsm4(bfr[nb_][nb], s + br0 + nb * 2048 + (ko ^ bxm));
            }
            if (kk == 2) {
                cp_wait<1>();
                __syncthreads();
            }
            const int cb = kk & 1;
#pragma unroll
            for (int mt = 0; mt < MT; mt++)
#pragma unroll
                for (int nt = 0; nt < 8; nt++)
                    mma16816(acc[mt][nt], afr[cb][mt],
                             bfr[cb][nt >> 1][(nt & 1) * 2],
                             bfr[cb][nt >> 1][(nt & 1) * 2 + 1]);
        }
        if (i + 1 < nch) {
            const uint32_t sn = sb + ((i + 1) % NST) * STG;
#pragma unroll
            for (int mt = 0; mt < MT; mt++)
                ldsm4(afr[0][mt], sn + ar0 + mt * 2048 + (0u ^ axm));
#pragma unroll
            for (int nb = 0; nb < 4; nb++)
                ldsm4(bfr[0][nb], sn + br0 + nb * 2048 + (0u ^ bxm));
        }
    }

    // exp epilogue: one f16x2 MUFU per pair, result = stored half2
    const int rr = lane >> 2, cc = 2 * (lane & 3);
    __half* cw = C + (size_t)(m0 + wm0) * ldc + (n0 + wn0);
#pragma unroll
    for (int mt = 0; mt < MT; mt++) {
        float sA = 0.f, sB = 0.f;
#pragma unroll
        for (int nt = 0; nt < 8; nt++) {
            const uint32_t e0 = ex2_f16x2(acc[mt][nt][0], acc[mt][nt][1]);
            const uint32_t e1 = ex2_f16x2(acc[mt][nt][2], acc[mt][nt][3]);
            *reinterpret_cast<uint32_t*>(cw + (size_t)(mt * 16 + rr) * ldc + nt * 8 + cc) = e0;
            *reinterpret_cast<uint32_t*>(cw + (size_t)(mt * 16 + rr + 8) * ldc + nt * 8 + cc) = e1;
            const float2 f0 = __half22float2(*reinterpret_cast<const __half2*>(&e0));
            const float2 f1 = __half22float2(*reinterpret_cast<const __half2*>(&e1));
            sA += f0.x + f0.y;
            sB += f1.x + f1.y;
        }
        sA += __shfl_xor_sync(0xFFFFFFFFu, sA, 1);
        sA += __shfl_xor_sync(0xFFFFFFFFu, sA, 2);
        sB += __shfl_xor_sync(0xFFFFFFFFu, sB, 1);
        sB += __shfl_xor_sync(0xFFFFFFFFu, sB, 2);
        if ((lane & 3) == 0) {
            atomicAdd(&l[m0 + wm0 + mt * 16 + rr], sA);
            atomicAdd(&l[m0 + wm0 + mt * 16 + rr + 8], sB);
        }
    }
}

// ================= GEMM2: 128x256, 256 thr, 1 CTA/SM, normalize =============
#define BNP 256
#define A_SM2 (128 * 128)
#define STG2 (A_SM2 + BNP * 128)             // 49152 B
#define SMEM_G2 (NST * STG2)                 // 147456 B

__global__ void __launch_bounds__(256, 1)
k_gemm2(const __half* __restrict__ A, const __half* __restrict__ B,
        float* __restrict__ C, float* __restrict__ l,
        int lda, int ldb, int ldc, int nch) {
    constexpr int MT = 4;

    extern __shared__ __align__(1024) char smem[];
    const uint32_t sb = smem_u32(smem);
    const int tid = threadIdx.x, lane = tid & 31, wid = tid >> 5;
    const int m0 = blockIdx.y * 128;          // N-fast raster
    const int n0 = blockIdx.x * BNP;

    const __half* arow = A + (size_t)m0 * lda;
    const __half* brow = B + (size_t)n0 * ldb;

    const int c_r0 = tid >> 3, c_ch = tid & 7;
    const int g = lane >> 3, lr = lane & 7;
    const int wm0 = (wid >> 2) * 64;          // 2 M-warps
    const int wn0 = (wid & 3) * 64;           // 4 N-warps
    const uint32_t alm = (uint32_t)(lr << 4);
    const uint32_t ar0 = (uint32_t)((wm0 + lr + (g & 1) * 8) * 128);
    const uint32_t axm = (uint32_t)((g >> 1) << 4) ^ alm;
    const uint32_t br0 = (uint32_t)(A_SM2 + (wn0 + lr + (g >> 1) * 8) * 128);
    const uint32_t bxm = (uint32_t)((g & 1) << 4) ^ alm;

    float acc[MT][8][4];
#pragma unroll
    for (int i = 0; i < MT; i++)
#pragma unroll
        for (int j = 0; j < 8; j++)
#pragma unroll
            for (int c = 0; c < 4; c++) acc[i][j][c] = 0.f;

#pragma unroll
    for (int j = 0; j < NST - 1; j++) {
        const uint32_t s = sb + j * STG2;
        const int kc = j * BK;
#pragma unroll
        for (int it = 0; it < 4; it++) {
            const int r = c_r0 + it * 32;
            cp16(s + r * 128 + ((c_ch ^ (r & 7)) << 4),
                 arow + (size_t)r * lda + kc + c_ch * 8);
        }
#pragma unroll
        for (int it = 0; it < 8; it++) {
            const int r = c_r0 + it * 32;
            cp16(s + A_SM2 + r * 128 + ((c_ch ^ (r & 7)) << 4),
                 brow + (size_t)r * ldb + kc + c_ch * 8);
        }
        cp_commit();
    }

    uint32_t afr[2][MT][4], bfr[2][4][4];
    cp_wait<NST - 2>();
    __syncthreads();
#pragma unroll
    for (int mt = 0; mt < MT; mt++)
        ldsm4(afr[0][mt], sb + ar0 + mt * 2048 + (0u ^ axm));
#pragma unroll
    for (int nb = 0; nb < 4; nb++)
        ldsm4(bfr[0][nb], sb + br0 + nb * 2048 + (0u ^ bxm));

    for (int i = 0; i < nch; i++) {
        const int jl = i + NST - 1;
        if (jl < nch) {
            const uint32_t s = sb + (jl % NST) * STG2;
            const int kc = jl * BK;
#pragma unroll
            for (int it = 0; it < 4; it++) {
                const int r = c_r0 + it * 32;
                cp16(s + r * 128 + ((c_ch ^ (r & 7)) << 4),
                     arow + (size_t)r * lda + kc + c_ch * 8);
            }
#pragma unroll
            for (int it = 0; it < 8; it++) {
                const int r = c_r0 + it * 32;
                cp16(s + A_SM2 + r * 128 + ((c_ch ^ (r & 7)) << 4),
                     brow + (size_t)r * ldb + kc + c_ch * 8);
            }
        }
        cp_commit();

        const uint32_t s = sb + (i % NST) * STG2;
#pragma unroll
        for (int kk = 0; kk < 4; kk++) {
            if (kk < 3) {
                const uint32_t ko = (uint32_t)((kk + 1) << 5);
                const int nb_ = (kk + 1) & 1;
#pragma unroll
                for (int mt = 0; mt < MT; mt++)
                    ldsm4(afr[nb_][mt], s + ar0 + mt * 2048 + (ko ^ axm));
#pragma unroll
                for (int nb = 0; nb < 4; nb++)
                    ldsm4(bfr[nb_][nb], s + br0 + nb * 2048 + (ko ^ bxm));
            }
            if (kk == 2) {
                cp_wait<1>();
                __syncthreads();
            }
            const int cb = kk & 1;
#pragma unroll
            for (int mt = 0; mt < MT; mt++)
#pragma unroll
                for (int nt = 0; nt < 8; nt++)
                    mma16816(acc[mt][nt], afr[cb][mt],
                             bfr[cb][nt >> 1][(nt & 1) * 2],
                             bfr[cb][nt >> 1][(nt & 1) * 2 + 1]);
        }
        if (i + 1 < nch) {
            const uint32_t sn = sb + ((i + 1) % NST) * STG2;
#pragma unroll
            for (int mt = 0; mt < MT; mt++)
                ldsm4(afr[0][mt], sn + ar0 + mt * 2048 + (0u ^ axm));
#pragma unroll
            for (int nb = 0; nb < 4; nb++)
                ldsm4(bfr[0][nb], sn + br0 + nb * 2048 + (0u ^ bxm));
        }
    }

    // normalize epilogue
    const int rr = lane >> 2, cc = 2 * (lane & 3);
    float* cw = C + (size_t)(m0 + wm0) * ldc + (n0 + wn0);

    float* ls = reinterpret_cast<float*>(smem);
    __syncthreads();
    if (tid < 128) ls[tid] = 1.f / l[m0 + tid];
    __syncthreads();
    float linv[MT][2];
#pragma unroll
    for (int mt = 0; mt < MT; mt++) {
        linv[mt][0] = ls[wm0 + mt * 16 + rr];
        linv[mt][1] = ls[wm0 + mt * 16 + rr + 8];
    }
#pragma unroll
    for (int mt = 0; mt < MT; mt++)
#pragma unroll
        for (int nt = 0; nt < 8; nt++) {
            float2 v0 = make_float2(acc[mt][nt][0] * linv[mt][0],
                                    acc[mt][nt][1] * linv[mt][0]);
            float2 v1 = make_float2(acc[mt][nt][2] * linv[mt][1],
                                    acc[mt][nt][3] * linv[mt][1]);
            *reinterpret_cast<float2*>(cw + (size_t)(mt * 16 + rr) * ldc + nt * 8 + cc) = v0;
            *reinterpret_cast<float2*>(cw + (size_t)(mt * 16 + rr + 8) * ldc + nt * 8 + cc) = v1;
        }
}

// ---------------- fused prep: zero l, cvt Q, cvt K, transpose V --------------
#define QK_BLKS (SQ * DM / 8 / 256)          // 4096
#define TR_BLKS ((DM / 32) * (SQ / 64))      // 4096

__global__ void __launch_bounds__(256)
k_prep(const float* __restrict__ q, const float* __restrict__ k,
       const float* __restrict__ v, __half* __restrict__ qh,
       __half* __restrict__ kh, __half* __restrict__ vt,
       float* __restrict__ l) {
    const int bx = blockIdx.x;
    if (bx < 2 * QK_BLKS) {
        const bool isq = bx < QK_BLKS;
        const int base = ((isq ? bx : bx - QK_BLKS) * 256 + threadIdx.x) * 2;
        const float sc = isq ? 0.045084937554f : 1.0f;   // log2e/32
        const float4* in = reinterpret_cast<const float4*>(isq ? q : k);
        __half2* o = reinterpret_cast<__half2*>(isq ? qh : kh);
#pragma unroll
        for (int u = 0; u < 2; u++) {
            float4 x = in[base + u];
            o[2 * (base + u)]     = __floats2half2_rn(x.x * sc, x.y * sc);
            o[2 * (base + u) + 1] = __floats2half2_rn(x.z * sc, x.w * sc);
        }
    } else if (bx < 2 * QK_BLKS + TR_BLKS) {
        __shared__ float tile[64][33];                   // [s_local][d_local]
        const int b = bx - 2 * QK_BLKS;
        const int d0 = (b % (DM / 32)) * 32, s0 = (b / (DM / 32)) * 64;
        const int tx = threadIdx.x & 31, ty = threadIdx.x >> 5;
#pragma unroll
        for (int i = 0; i < 8; i++)
            tile[ty + i * 8][tx] = v[(size_t)(s0 + ty + i * 8) * DM + d0 + tx];
        __syncthreads();
        __half2* vt2 = reinterpret_cast<__half2*>(vt);
#pragma unroll
        for (int j = 0; j < 4; j++) {
            const int dl = ty + j * 8;
            vt2[(size_t)(d0 + dl) * (SQ / 2) + s0 / 2 + tx] =
                __floats2half2_rn(tile[2 * tx][dl], tile[2 * tx + 1][dl]);
        }
    } else {
        const int i = (bx - 2 * QK_BLKS - TR_BLKS) * 256 + threadIdx.x;
        l[i] = 0.f;
    }
}

// ---------------- launcher ---------------------------------------------------
extern "C" void kernel_launch(void* const* d_in, const int* in_sizes, int n_in,
                              void* d_out, int out_size) {
    const float* q = (const float*)d_in[0];
    const float* k = (const float*)d_in[1];
    const float* v = (const float*)d_in[2];
    float* out = (float*)d_out;

    __half *qh, *kh, *vt, *p;
    float* l;
    cudaGetSymbolAddress((void**)&qh, g_qh);
    cudaGetSymbolAddress((void**)&kh, g_kh);
    cudaGetSymbolAddress((void**)&vt, g_vt);
    cudaGetSymbolAddress((void**)&p,  g_p);
    cudaGetSymbolAddress((void**)&l,  g_l);

    constexpr int SMEM1 = NST * (128 * 128 + 128 * 128);   // 98304 B

    cudaFuncSetAttribute((void*)k_gemm1,
                         cudaFuncAttributeMaxDynamicSharedMemorySize, SMEM1);
    cudaFuncSetAttribute((void*)k_gemm2,
                         cudaFuncAttributeMaxDynamicSharedMemorySize, SMEM_G2);

    // fused prep: cvt Q (scaled), cvt K, transpose V, zero l
    k_prep<<<2 * QK_BLKS + TR_BLKS + SQ / 256, 256>>>(q, k, v, qh, kh, vt, l);

    // P' = exp2(Qs K^T) : M=N=8192, K=1024 -> fp16, row sums -> l
    k_gemm1<<<dim3(SQ / 128, SQ / 128), 128, SMEM1>>>(
        qh, kh, p, l, DM, DM, SQ, DM / BK);

    // out = (P' V) / l : M=8192, N=1024, K=8192 -> fp32 (N-fast raster)
    k_gemm2<<<dim3(DM / BNP, SQ / 128), 256, SMEM_G2>>>(
        p, vt, out, l, SQ, SQ, DM, SQ / BK);
}